// round 2
// baseline (speedup 1.0000x reference)
#include <cuda_runtime.h>
#include <cstdint>
#include <cstddef>

// Problem constants
#define Bq 8
#define Nq 2048
#define Kq 32
#define Fq 256          // F_IN = F_OUT = 256
#define Cq 512          // 2*F_OUT
#define Mq (Bq*Nq)      // 16384 rows

// Scratch (no cudaMalloc allowed)
__device__ float g_xn[(size_t)Mq * Fq];   // gathered neighbor means, 16 MB
__device__ float g_sum[Cq];
__device__ float g_sumsq[Cq];
__device__ float g_scale[Cq];
__device__ float g_shift[Cq];

typedef unsigned long long u64;

__device__ __forceinline__ u64 ffma2(u64 a, u64 b, u64 c) {
    u64 d;
    asm("fma.rn.f32x2 %0, %1, %2, %3;" : "=l"(d) : "l"(a), "l"(b), "l"(c));
    return d;
}

// ---------------------------------------------------------------------------
// Kernel 1: gather + mean over 32 neighbors. 4 rows/block, 64 f4-lanes/row.
// Block 0 also zeroes the BN stat accumulators (ALL 512 channels).
// ---------------------------------------------------------------------------
__global__ __launch_bounds__(256) void k_gather(const float4* __restrict__ x4,
                                                const int* __restrict__ idx,
                                                float4* __restrict__ xn4) {
    if (blockIdx.x == 0) {
        const int c = threadIdx.x;          // 256 threads -> 2 entries each
        g_sum[c] = 0.f;         g_sum[c + 256] = 0.f;
        g_sumsq[c] = 0.f;       g_sumsq[c + 256] = 0.f;
    }
    __shared__ int nbr[4][Kq];
    const int tid = threadIdx.x;
    const int rr = tid >> 6;          // row within block, 0..3
    const int q  = tid & 63;          // float4 lane within row
    const int r  = blockIdx.x * 4 + rr;   // global row = b*N + n
    const int b  = r >> 11;           // N = 2048

    if (tid < 128) {
        int k   = tid & 31;
        int rr2 = tid >> 5;
        int n2  = (blockIdx.x * 4 + rr2) & (Nq - 1);
        nbr[rr2][k] = idx[n2 * Kq + k];
    }
    __syncthreads();

    const float4* xb = x4 + (size_t)b * Nq * (Fq / 4);
    float4 acc = make_float4(0.f, 0.f, 0.f, 0.f);
#pragma unroll 8
    for (int k = 0; k < Kq; k++) {
        float4 v = xb[(size_t)nbr[rr][k] * (Fq / 4) + q];
        acc.x += v.x; acc.y += v.y; acc.z += v.z; acc.w += v.w;
    }
    const float s = 1.f / 32.f;
    acc.x *= s; acc.y *= s; acc.z *= s; acc.w *= s;
    xn4[(size_t)r * (Fq / 4) + q] = acc;
}

// ---------------------------------------------------------------------------
// Kernel 2: dual GEMM (packed f32x2: .x = self, .y = neighbor) + bias
//           + per-row L2 normalize + ReLU + write out + BN stat accumulation.
// Block tile: 64 rows x 256 channel-pairs. 256 threads = 8 warps.
// Per warp: 8 rows (exclusive). Per thread: 8 rows x 8 pairs in registers.
// ---------------------------------------------------------------------------
#define MT 64
#define KT 32
#define WPITCH 257     // float2 pitch for sW rows (conflict-free b reads)
#define XPITCH 33      // float2 pitch for sX rows
#define SMEM2 ((size_t)(KT*WPITCH + MT*XPITCH + 2*256) * sizeof(float2))

__global__ __launch_bounds__(256, 1) void k_gemm(const float* __restrict__ x,
                                                 const float* __restrict__ Wx,
                                                 const float* __restrict__ Wn,
                                                 const float* __restrict__ bx,
                                                 const float* __restrict__ bn,
                                                 float* __restrict__ out) {
    extern __shared__ char smem_raw[];
    float2* sW   = (float2*)smem_raw;                         // [KT][WPITCH]
    float2* sX   = sW + KT * WPITCH;                          // [MT][XPITCH]
    float2* redS = sX + MT * XPITCH;                          // [256]
    float2* redQ = redS + 256;                                // [256]

    const int tid  = threadIdx.x;
    const int lane = tid & 31;
    const int w    = tid >> 5;                 // warp id 0..7
    const int row0 = blockIdx.x * MT;

    redS[tid] = make_float2(0.f, 0.f);
    redQ[tid] = make_float2(0.f, 0.f);

    u64 acc[8][8];
#pragma unroll
    for (int i = 0; i < 8; i++)
#pragma unroll
        for (int j = 0; j < 8; j++) acc[i][j] = 0ull;

    const float* xrow  = x    + (size_t)row0 * Fq;
    const float* xnrow = g_xn + (size_t)row0 * Fq;

    for (int k0 = 0; k0 < Fq; k0 += KT) {
        __syncthreads();   // prior compute done before overwriting tiles
        // Load W tile: sW[k][c] = {Wx[c][k0+k], Wn[c][k0+k]}
        {
            const int k  = tid & 31;
            const int cb = tid >> 5;           // 0..7
#pragma unroll
            for (int i = 0; i < 32; i++) {
                int c = cb + i * 8;
                sW[k * WPITCH + c] =
                    make_float2(Wx[c * Fq + k0 + k], Wn[c * Fq + k0 + k]);
            }
        }
        // Load X tile: sX[m][k] = {x[m][k0+k], xn[m][k0+k]}
        {
            const int k  = tid & 31;
            const int mb = tid >> 5;           // 0..7
#pragma unroll
            for (int i = 0; i < 8; i++) {
                int m = mb + i * 8;
                sX[m * XPITCH + k] =
                    make_float2(xrow[(size_t)m * Fq + k0 + k],
                                xnrow[(size_t)m * Fq + k0 + k]);
            }
        }
        __syncthreads();

#pragma unroll 4
        for (int kk = 0; kk < KT; kk++) {
            u64 a[8], b[8];
#pragma unroll
            for (int i = 0; i < 8; i++)
                a[i] = *(const u64*)&sX[(w * 8 + i) * XPITCH + kk];
#pragma unroll
            for (int j = 0; j < 8; j++)
                b[j] = *(const u64*)&sW[kk * WPITCH + lane + 32 * j];
#pragma unroll
            for (int i = 0; i < 8; i++)
#pragma unroll
                for (int j = 0; j < 8; j++)
                    acc[i][j] = ffma2(a[i], b[j], acc[i][j]);
        }
    }

    // Epilogue: bias, L2-normalize over 512 channels (row is warp-exclusive),
    // ReLU, store, accumulate BN stats.
    float2 bias[8];
#pragma unroll
    for (int j = 0; j < 8; j++)
        bias[j] = make_float2(bx[lane + 32 * j], bn[lane + 32 * j]);

    float2 ps[8], pq[8];
#pragma unroll
    for (int j = 0; j < 8; j++) {
        ps[j] = make_float2(0.f, 0.f);
        pq[j] = make_float2(0.f, 0.f);
    }

#pragma unroll
    for (int i = 0; i < 8; i++) {
        const int m = row0 + w * 8 + i;
        float2 v[8];
        float ss = 0.f;
#pragma unroll
        for (int j = 0; j < 8; j++) {
            v[j] = *(float2*)&acc[i][j];
            v[j].x += bias[j].x;
            v[j].y += bias[j].y;
            ss += v[j].x * v[j].x + v[j].y * v[j].y;
        }
#pragma unroll
        for (int off = 16; off > 0; off >>= 1)
            ss += __shfl_xor_sync(0xffffffffu, ss, off);
        const float rn = 1.f / fmaxf(sqrtf(ss), 1e-12f);
        float* orow = out + (size_t)m * Cq;
#pragma unroll
        for (int j = 0; j < 8; j++) {
            float hx = fmaxf(v[j].x * rn, 0.f);
            float hn = fmaxf(v[j].y * rn, 0.f);
            orow[lane + 32 * j]       = hx;
            orow[256 + lane + 32 * j] = hn;
            ps[j].x += hx;      ps[j].y += hn;
            pq[j].x += hx * hx; pq[j].y += hn * hn;
        }
    }

#pragma unroll
    for (int j = 0; j < 8; j++) {
        const int c = lane + 32 * j;
        atomicAdd(&redS[c].x, ps[j].x);
        atomicAdd(&redS[c].y, ps[j].y);
        atomicAdd(&redQ[c].x, pq[j].x);
        atomicAdd(&redQ[c].y, pq[j].y);
    }
    __syncthreads();
    if (tid < 256) {
        atomicAdd(&g_sum[tid],         redS[tid].x);
        atomicAdd(&g_sum[tid + 256],   redS[tid].y);
        atomicAdd(&g_sumsq[tid],       redQ[tid].x);
        atomicAdd(&g_sumsq[tid + 256], redQ[tid].y);
    }
}

// ---------------------------------------------------------------------------
// Kernel 3: fold BN stats into per-channel scale/shift.
// ---------------------------------------------------------------------------
__global__ void k_stats(const float* __restrict__ gamma,
                        const float* __restrict__ beta) {
    const int c = threadIdx.x;   // 512 threads
    const float inv_n = 1.f / (float)Mq;
    float mu  = g_sum[c] * inv_n;
    float var = fmaxf(g_sumsq[c] * inv_n - mu * mu, 0.f);
    float inv = rsqrtf(var + 1e-5f);
    float sc  = gamma[c] * inv;
    g_scale[c] = sc;
    g_shift[c] = beta[c] - mu * sc;
}

// ---------------------------------------------------------------------------
// Kernel 4: apply BN elementwise in place (float4).
// ---------------------------------------------------------------------------
__global__ __launch_bounds__(256) void k_apply(float4* __restrict__ out4) {
    const size_t i = (size_t)blockIdx.x * blockDim.x + threadIdx.x;
    const int c = (int)(i & 127) * 4;     // 128 float4 per row of 512 channels
    float4 v = out4[i];
    v.x = v.x * g_scale[c + 0] + g_shift[c + 0];
    v.y = v.y * g_scale[c + 1] + g_shift[c + 1];
    v.z = v.z * g_scale[c + 2] + g_shift[c + 2];
    v.w = v.w * g_scale[c + 3] + g_shift[c + 3];
    out4[i] = v;
}

// ---------------------------------------------------------------------------
extern "C" void kernel_launch(void* const* d_in, const int* in_sizes, int n_in,
                              void* d_out, int out_size) {
    const float* x     = (const float*)d_in[0];
    const int*   idx   = (const int*)  d_in[1];
    const float* Wx    = (const float*)d_in[2];
    const float* bx    = (const float*)d_in[3];
    const float* Wn    = (const float*)d_in[4];
    const float* bn    = (const float*)d_in[5];
    const float* gamma = (const float*)d_in[6];
    const float* beta  = (const float*)d_in[7];
    float* out = (float*)d_out;

    cudaFuncSetAttribute(k_gemm, cudaFuncAttributeMaxDynamicSharedMemorySize,
                         (int)SMEM2);

    float4* xn4;
    cudaGetSymbolAddress((void**)&xn4, g_xn);

    k_gather<<<Mq / 4, 256>>>((const float4*)x, idx, xn4);
    k_gemm<<<Mq / MT, 256, SMEM2>>>(x, Wx, Wn, bx, bn, out);
    k_stats<<<1, Cq>>>(gamma, beta);
    k_apply<<<(Mq * (Cq / 4)) / 256, 256>>>((float4*)out);
}

// round 3
// speedup vs baseline: 1.5520x; 1.5520x over previous
#include <cuda_runtime.h>
#include <cstdint>
#include <cstddef>

// Problem constants
#define Bq 8
#define Nq 2048
#define Kq 32
#define Fq 256          // F_IN = F_OUT = 256
#define Cq 512          // 2*F_OUT
#define Mq (Bq*Nq)      // 16384 rows

// Scratch (no cudaMalloc allowed)
__device__ float g_xn[(size_t)Mq * Fq];   // gathered neighbor means, 16 MB
__device__ float g_sum[Cq];
__device__ float g_sumsq[Cq];
__device__ float4 g_scale4[Cq / 4];
__device__ float4 g_shift4[Cq / 4];

typedef unsigned long long u64;

__device__ __forceinline__ u64 ffma2(u64 a, u64 b, u64 c) {
    u64 d;
    asm("fma.rn.f32x2 %0, %1, %2, %3;" : "=l"(d) : "l"(a), "l"(b), "l"(c));
    return d;
}

// ---------------------------------------------------------------------------
// Kernel 1: gather + mean over 32 neighbors. 4 rows/block, 64 f4-lanes/row.
// Block 0 also zeroes the BN stat accumulators (ALL 512 channels).
// ---------------------------------------------------------------------------
__global__ __launch_bounds__(256) void k_gather(const float4* __restrict__ x4,
                                                const int* __restrict__ idx,
                                                float4* __restrict__ xn4) {
    if (blockIdx.x == 0) {
        const int c = threadIdx.x;          // 256 threads -> 2 entries each
        g_sum[c] = 0.f;         g_sum[c + 256] = 0.f;
        g_sumsq[c] = 0.f;       g_sumsq[c + 256] = 0.f;
    }
    __shared__ int nbr[4][Kq];
    const int tid = threadIdx.x;
    const int rr = tid >> 6;          // row within block, 0..3
    const int q  = tid & 63;          // float4 lane within row
    const int r  = blockIdx.x * 4 + rr;   // global row = b*N + n
    const int b  = r >> 11;           // N = 2048

    if (tid < 128) {
        int k   = tid & 31;
        int rr2 = tid >> 5;
        int n2  = (blockIdx.x * 4 + rr2) & (Nq - 1);
        nbr[rr2][k] = idx[n2 * Kq + k];
    }
    __syncthreads();

    const float4* xb = x4 + (size_t)b * Nq * (Fq / 4);
    float4 acc = make_float4(0.f, 0.f, 0.f, 0.f);
#pragma unroll 8
    for (int k = 0; k < Kq; k++) {
        float4 v = xb[(size_t)nbr[rr][k] * (Fq / 4) + q];
        acc.x += v.x; acc.y += v.y; acc.z += v.z; acc.w += v.w;
    }
    const float s = 1.f / 32.f;
    acc.x *= s; acc.y *= s; acc.z *= s; acc.w *= s;
    xn4[(size_t)r * (Fq / 4) + q] = acc;
}

// ---------------------------------------------------------------------------
// Kernel 2: dual GEMM (packed f32x2: .x = self, .y = neighbor) + bias
//           + per-row L2 normalize + ReLU + write out + BN stat accumulation.
// Block tile: 64 rows x 256 channel-pairs. 512 threads = 16 warps.
// Warp w: rows (w&7)*8..+8, channel quarter (w>>3)*4 pair-groups.
// Per thread: 8 rows x 4 pairs in registers (64 acc regs).
// ---------------------------------------------------------------------------
#define MT 64
#define KT 32
#define WPITCH 257     // float2 pitch for sW rows
#define XPITCH 33      // float2 pitch for sX rows
#define NSS   (MT * 2) // row-norm partials: [row][half]
#define SMEM2 ((size_t)(KT*WPITCH + MT*XPITCH + 2*256) * sizeof(float2) + NSS * sizeof(float))

__global__ __launch_bounds__(512, 1) void k_gemm(const float* __restrict__ x,
                                                 const float* __restrict__ Wx,
                                                 const float* __restrict__ Wn,
                                                 const float* __restrict__ bx,
                                                 const float* __restrict__ bn,
                                                 float* __restrict__ out) {
    extern __shared__ char smem_raw[];
    float2* sW   = (float2*)smem_raw;                         // [KT][WPITCH]
    float2* sX   = sW + KT * WPITCH;                          // [MT][XPITCH]
    float2* redS = sX + MT * XPITCH;                          // [256]
    float2* redQ = redS + 256;                                // [256]
    float*  ssb  = (float*)(redQ + 256);                      // [MT][2]

    const int tid  = threadIdx.x;
    const int lane = tid & 31;
    const int w    = tid >> 5;                 // warp id 0..15
    const int wr   = w & 7;                    // row group
    const int wh   = w >> 3;                   // channel half (j offset 4*wh)
    const int row0 = blockIdx.x * MT;

    if (tid < 256) {
        redS[tid] = make_float2(0.f, 0.f);
        redQ[tid] = make_float2(0.f, 0.f);
    }

    u64 acc[8][4];
#pragma unroll
    for (int i = 0; i < 8; i++)
#pragma unroll
        for (int j = 0; j < 4; j++) acc[i][j] = 0ull;

    const float* xrow  = x    + (size_t)row0 * Fq;
    const float* xnrow = g_xn + (size_t)row0 * Fq;
    const int cbase = lane + 128 * wh;         // channel of pair j=0

    for (int k0 = 0; k0 < Fq; k0 += KT) {
        __syncthreads();   // prior compute done before overwriting tiles
        // Load W tile: sW[k][c] = {Wx[c][k0+k], Wn[c][k0+k]}  (512 thr, 16 ea)
        {
            const int k  = tid & 31;
            const int cb = tid >> 5;           // 0..15
#pragma unroll
            for (int i = 0; i < 16; i++) {
                int c = cb + i * 16;
                sW[k * WPITCH + c] =
                    make_float2(Wx[c * Fq + k0 + k], Wn[c * Fq + k0 + k]);
            }
        }
        // Load X tile: sX[m][k] = {x[m][k0+k], xn[m][k0+k]}  (512 thr, 4 ea)
        {
            const int k  = tid & 31;
            const int mb = tid >> 5;           // 0..15
#pragma unroll
            for (int i = 0; i < 4; i++) {
                int m = mb + i * 16;
                sX[m * XPITCH + k] =
                    make_float2(xrow[(size_t)m * Fq + k0 + k],
                                xnrow[(size_t)m * Fq + k0 + k]);
            }
        }
        __syncthreads();

#pragma unroll 4
        for (int kk = 0; kk < KT; kk++) {
            u64 a[8], b[4];
#pragma unroll
            for (int i = 0; i < 8; i++)
                a[i] = *(const u64*)&sX[(wr * 8 + i) * XPITCH + kk];
#pragma unroll
            for (int j = 0; j < 4; j++)
                b[j] = *(const u64*)&sW[kk * WPITCH + cbase + 32 * j];
#pragma unroll
            for (int i = 0; i < 8; i++)
#pragma unroll
                for (int j = 0; j < 4; j++)
                    acc[i][j] = ffma2(a[i], b[j], acc[i][j]);
        }
    }

    // ---- Epilogue ----
    float2 bias[4];
#pragma unroll
    for (int j = 0; j < 4; j++)
        bias[j] = make_float2(bx[cbase + 32 * j], bn[cbase + 32 * j]);

    // Phase 1: bias + per-row partial sum of squares (this warp's 128 pairs)
    float2 v[8][4];
#pragma unroll
    for (int i = 0; i < 8; i++) {
        float ss = 0.f;
#pragma unroll
        for (int j = 0; j < 4; j++) {
            v[i][j] = *(float2*)&acc[i][j];
            v[i][j].x += bias[j].x;
            v[i][j].y += bias[j].y;
            ss += v[i][j].x * v[i][j].x + v[i][j].y * v[i][j].y;
        }
#pragma unroll
        for (int off = 16; off > 0; off >>= 1)
            ss += __shfl_xor_sync(0xffffffffu, ss, off);
        if (lane == 0) ssb[(wr * 8 + i) * 2 + wh] = ss;
    }
    __syncthreads();

    // Phase 2: normalize, relu, store, accumulate stats
    float2 ps[4], pq[4];
#pragma unroll
    for (int j = 0; j < 4; j++) {
        ps[j] = make_float2(0.f, 0.f);
        pq[j] = make_float2(0.f, 0.f);
    }
#pragma unroll
    for (int i = 0; i < 8; i++) {
        const int mr = wr * 8 + i;
        const float sstot = ssb[mr * 2] + ssb[mr * 2 + 1];
        const float rn = 1.f / fmaxf(sqrtf(sstot), 1e-12f);
        float* orow = out + (size_t)(row0 + mr) * Cq;
#pragma unroll
        for (int j = 0; j < 4; j++) {
            float hx = fmaxf(v[i][j].x * rn, 0.f);
            float hn = fmaxf(v[i][j].y * rn, 0.f);
            orow[cbase + 32 * j]       = hx;
            orow[256 + cbase + 32 * j] = hn;
            ps[j].x += hx;      ps[j].y += hn;
            pq[j].x += hx * hx; pq[j].y += hn * hn;
        }
    }

#pragma unroll
    for (int j = 0; j < 4; j++) {
        const int c = cbase + 32 * j;
        atomicAdd(&redS[c].x, ps[j].x);
        atomicAdd(&redS[c].y, ps[j].y);
        atomicAdd(&redQ[c].x, pq[j].x);
        atomicAdd(&redQ[c].y, pq[j].y);
    }
    __syncthreads();
    if (tid < 256) {
        atomicAdd(&g_sum[tid],         redS[tid].x);
        atomicAdd(&g_sum[tid + 256],   redS[tid].y);
        atomicAdd(&g_sumsq[tid],       redQ[tid].x);
        atomicAdd(&g_sumsq[tid + 256], redQ[tid].y);
    }
}

// ---------------------------------------------------------------------------
// Kernel 3: fold BN stats into per-channel scale/shift.
// ---------------------------------------------------------------------------
__global__ void k_stats(const float* __restrict__ gamma,
                        const float* __restrict__ beta) {
    const int c = threadIdx.x;   // 512 threads
    const float inv_n = 1.f / (float)Mq;
    float mu  = g_sum[c] * inv_n;
    float var = fmaxf(g_sumsq[c] * inv_n - mu * mu, 0.f);
    float inv = rsqrtf(var + 1e-5f);
    float sc  = gamma[c] * inv;
    ((float*)g_scale4)[c] = sc;
    ((float*)g_shift4)[c] = beta[c] - mu * sc;
}

// ---------------------------------------------------------------------------
// Kernel 4: apply BN elementwise in place (float4 data AND float4 params).
// ---------------------------------------------------------------------------
__global__ __launch_bounds__(256) void k_apply(float4* __restrict__ out4) {
    const size_t i = (size_t)blockIdx.x * blockDim.x + threadIdx.x;
    const int p = (int)(i & 127);         // float4 index within 512-ch row
    const float4 sc = g_scale4[p];
    const float4 sh = g_shift4[p];
    float4 v = out4[i];
    v.x = v.x * sc.x + sh.x;
    v.y = v.y * sc.y + sh.y;
    v.z = v.z * sc.z + sh.z;
    v.w = v.w * sc.w + sh.w;
    out4[i] = v;
}

// ---------------------------------------------------------------------------
extern "C" void kernel_launch(void* const* d_in, const int* in_sizes, int n_in,
                              void* d_out, int out_size) {
    const float* x     = (const float*)d_in[0];
    const int*   idx   = (const int*)  d_in[1];
    const float* Wx    = (const float*)d_in[2];
    const float* bx    = (const float*)d_in[3];
    const float* Wn    = (const float*)d_in[4];
    const float* bn    = (const float*)d_in[5];
    const float* gamma = (const float*)d_in[6];
    const float* beta  = (const float*)d_in[7];
    float* out = (float*)d_out;

    cudaFuncSetAttribute(k_gemm, cudaFuncAttributeMaxDynamicSharedMemorySize,
                         (int)SMEM2);

    float4* xn4;
    cudaGetSymbolAddress((void**)&xn4, g_xn);

    k_gather<<<Mq / 4, 256>>>((const float4*)x, idx, xn4);
    k_gemm<<<Mq / MT, 512, SMEM2>>>(x, Wx, Wn, bx, bn, out);
    k_stats<<<1, Cq>>>(gamma, beta);
    k_apply<<<(Mq * (Cq / 4)) / 256, 256>>>((float4*)out);
}